// round 1
// baseline (speedup 1.0000x reference)
#include <cuda_runtime.h>
#include <cuda_bf16.h>

// Problem constants (fixed shapes for this problem)
#define N_NODES 65536
#define N_EDGES 1048576
#define C_IN    22
#define H_DIM   64
#define B_SZ    16
#define L_SEQ   4096      // N_NODES / B_SZ
#define T_CH    32
#define KW      3
#define L1_OUT  4098      // L + 2*2 - 2
#define L2_OUT  4100
#define NCLS    3

// ---------------- scratch (static device globals; no allocations) ----------
__device__ float g_buf0[N_NODES * H_DIM];   // pre-aggregation features
__device__ float g_buf1[N_NODES * H_DIM];   // aggregation target / activated h
__device__ float g_dinv[N_NODES];           // deg, then rsqrt(deg)
__device__ float g_norm[N_EDGES];           // per-edge normalization
__device__ float g_y1[B_SZ * T_CH * L1_OUT];
__device__ float g_y2[B_SZ * T_CH * L2_OUT];
__device__ float g_stats[4 * T_CH];         // mean1, rstd1, mean2, rstd2
__device__ float g_pool[B_SZ * T_CH];

// ---------------- degree / normalization ----------------
__global__ void k_deg_init() {
    int i = blockIdx.x * blockDim.x + threadIdx.x;
    if (i < N_NODES) g_dinv[i] = 1.0f;  // self-loop weight
}

__global__ void k_deg_add(const int* __restrict__ ei, const float* __restrict__ ew) {
    int e = blockIdx.x * blockDim.x + threadIdx.x;
    if (e < N_EDGES) atomicAdd(&g_dinv[ei[N_EDGES + e]], ew[e]);
}

__global__ void k_dinv() {
    int i = blockIdx.x * blockDim.x + threadIdx.x;
    if (i < N_NODES) g_dinv[i] = rsqrtf(g_dinv[i]);  // deg >= 1 always
}

__global__ void k_norm(const int* __restrict__ ei, const float* __restrict__ ew) {
    int e = blockIdx.x * blockDim.x + threadIdx.x;
    if (e < N_EDGES) {
        int r = ei[e], c = ei[N_EDGES + e];
        g_norm[e] = g_dinv[r] * ew[e] * g_dinv[c];
    }
}

// ---------------- x @ W1 -> buf0 ----------------
__global__ void k_gemm1(const float* __restrict__ x, const float* __restrict__ W1) {
    __shared__ float sW[C_IN * H_DIM];
    __shared__ float sx[4 * C_IN];
    int t = threadIdx.x;
    for (int i = t; i < C_IN * H_DIM; i += 256) sW[i] = W1[i];
    int n0 = blockIdx.x * 4;
    for (int i = t; i < 4 * C_IN; i += 256) sx[i] = x[n0 * C_IN + i];
    __syncthreads();
    int n = t >> 6, f = t & 63;
    float acc = 0.f;
#pragma unroll
    for (int c = 0; c < C_IN; c++) acc += sx[n * C_IN + c] * sW[c * H_DIM + f];
    g_buf0[(n0 + n) * H_DIM + f] = acc;
}

// ---------------- relu(h1) @ W2 -> buf0 (reads buf1) ----------------
__global__ void k_gemm2(const float* __restrict__ W2) {
    __shared__ float sW[H_DIM * H_DIM];
    __shared__ float sh[4 * H_DIM];
    int t = threadIdx.x;
    for (int i = t; i < H_DIM * H_DIM; i += 256) sW[i] = W2[i];
    int n0 = blockIdx.x * 4;
    sh[t] = g_buf1[n0 * H_DIM + t];
    __syncthreads();
    int n = t >> 6, f = t & 63;
    float acc = 0.f;
#pragma unroll
    for (int c = 0; c < H_DIM; c++) acc += sh[n * H_DIM + c] * sW[c * H_DIM + f];
    g_buf0[(n0 + n) * H_DIM + f] = acc;
}

// ---------------- zero aggregation buffer ----------------
__global__ void k_zero() {
    int i = blockIdx.x * blockDim.x + threadIdx.x;
    if (i < N_NODES * H_DIM / 4)
        reinterpret_cast<float4*>(g_buf1)[i] = make_float4(0.f, 0.f, 0.f, 0.f);
}

// ---------------- edge scatter: buf1[col] += norm * buf0[row] ----------------
__global__ void k_scatter(const int* __restrict__ ei) {
    int idx = blockIdx.x * blockDim.x + threadIdx.x;
    int e = idx >> 4;
    int lane = idx & 15;
    if (e >= N_EDGES) return;
    int r = ei[e];
    int c = ei[N_EDGES + e];
    float w = g_norm[e];
    float4 v = reinterpret_cast<const float4*>(g_buf0)[r * 16 + lane];
    float* p = g_buf1 + c * 64 + lane * 4;
    asm volatile("red.global.add.v4.f32 [%0], {%1,%2,%3,%4};"
                 :: "l"(p), "f"(v.x * w), "f"(v.y * w), "f"(v.z * w), "f"(v.w * w)
                 : "memory");
}

// ---------------- self-loop + bias + relu (in-place on buf1) ----------------
__global__ void k_post(const float* __restrict__ bias) {
    int i = blockIdx.x * blockDim.x + threadIdx.x;
    if (i >= N_NODES * H_DIM) return;
    int n = i >> 6;
    float d = g_dinv[n];
    float v = g_buf1[i] + d * d * g_buf0[i] + bias[i & 63];
    g_buf1[i] = fmaxf(v, 0.f);
}

// ---------------- conv1: [B,64,L] -> y1 [B,32,L1_OUT] ----------------
__global__ void k_conv1(const float* __restrict__ w, const float* __restrict__ bias) {
    __shared__ float sx[10 * 64];          // rows t0-2..t0+7, 64 channels
    __shared__ float sw[192 * 33];         // sw[(i*3+k)*33 + o]
    int b = blockIdx.y;
    int t0 = blockIdx.x * 8;
    int t = threadIdx.x;
    for (int j = t; j < T_CH * H_DIM * KW; j += 256) {
        int o = j / 192, ik = j % 192;
        sw[ik * 33 + o] = w[j];
    }
    for (int j = t; j < 640; j += 256) {
        int row = j >> 6, c = j & 63;
        int l = t0 + row - 2;
        sx[j] = (l >= 0 && l < L_SEQ) ? g_buf1[((b << 12) + l) * 64 + c] : 0.f;
    }
    __syncthreads();
    int o = t & 31, tl = t >> 5;
    int tt = t0 + tl;
    if (tt >= L1_OUT) return;
    float acc = bias[o];
#pragma unroll
    for (int k = 0; k < KW; k++)
#pragma unroll
        for (int i = 0; i < H_DIM; i++)
            acc += sx[(tl + k) * 64 + i] * sw[(i * 3 + k) * 33 + o];
    g_y1[(b * T_CH + o) * L1_OUT + tt] = acc;
}

// ---------------- BN stats (mean / rstd per channel) ----------------
__global__ void k_stats(int which) {
    const float* y = which ? g_y2 : g_y1;
    const int Lout = which ? L2_OUT : L1_OUT;
    const int base = which ? 64 : 0;
    int o = blockIdx.x;
    long long n = (long long)B_SZ * Lout;
    double s = 0.0, sq = 0.0;
    for (int b = 0; b < B_SZ; b++) {
        const float* p = y + (b * T_CH + o) * Lout;
        for (int i = threadIdx.x; i < Lout; i += 256) {
            float v = p[i];
            s += v;
            sq += (double)v * v;
        }
    }
    __shared__ double ss[256], ssq[256];
    ss[threadIdx.x] = s; ssq[threadIdx.x] = sq;
    __syncthreads();
    for (int st = 128; st > 0; st >>= 1) {
        if (threadIdx.x < st) { ss[threadIdx.x] += ss[threadIdx.x + st]; ssq[threadIdx.x] += ssq[threadIdx.x + st]; }
        __syncthreads();
    }
    if (threadIdx.x == 0) {
        double m = ss[0] / (double)n;
        double var = ssq[0] / (double)n - m * m;
        g_stats[base + o] = (float)m;
        g_stats[base + 32 + o] = (float)rsqrt(var + 1e-5);
    }
}

// ---------------- conv2: reads y1 with BN1 affine + relu applied on the fly ----
__global__ void k_conv2(const float* __restrict__ w, const float* __restrict__ bias,
                        const float* __restrict__ g1, const float* __restrict__ be1) {
    __shared__ float sx[32 * 10];          // sx[i*10 + row]
    __shared__ float sw[96 * 33];          // sw[(i*3+k)*33 + o]
    int b = blockIdx.y;
    int t0 = blockIdx.x * 8;
    int t = threadIdx.x;
    for (int j = t; j < T_CH * T_CH * KW; j += 256) {
        int o = j / 96, ik = j % 96;
        sw[ik * 33 + o] = w[j];
    }
    for (int j = t; j < 320; j += 256) {
        int i = j / 10, row = j % 10;
        int l = t0 + row - 2;
        float v = 0.f;
        if (l >= 0 && l < L1_OUT) {
            float m = g_stats[i], rs = g_stats[32 + i];
            float ga = g1[i] * rs;
            float bb = be1[i] - m * ga;
            v = fmaxf(g_y1[(b * T_CH + i) * L1_OUT + l] * ga + bb, 0.f);
        }
        sx[j] = v;
    }
    __syncthreads();
    int o = t & 31, tl = t >> 5;
    int tt = t0 + tl;
    if (tt >= L2_OUT) return;
    float acc = bias[o];
#pragma unroll
    for (int k = 0; k < KW; k++)
#pragma unroll
        for (int i = 0; i < T_CH; i++)
            acc += sx[i * 10 + tl + k] * sw[(i * 3 + k) * 33 + o];
    g_y2[(b * T_CH + o) * L2_OUT + tt] = acc;
}

// ---------------- BN2 affine + relu + mean over time -> g_pool ----------------
__global__ void k_pool(const float* __restrict__ g2, const float* __restrict__ be2) {
    int b = blockIdx.x >> 5, o = blockIdx.x & 31;
    float m = g_stats[64 + o], rs = g_stats[96 + o];
    float ga = g2[o] * rs;
    float bb = be2[o] - m * ga;
    const float* y = g_y2 + (b * T_CH + o) * L2_OUT;
    float s = 0.f;
    for (int i = threadIdx.x; i < L2_OUT; i += 256) s += fmaxf(y[i] * ga + bb, 0.f);
    __shared__ float sm[256];
    sm[threadIdx.x] = s;
    __syncthreads();
    for (int st = 128; st > 0; st >>= 1) {
        if (threadIdx.x < st) sm[threadIdx.x] += sm[threadIdx.x + st];
        __syncthreads();
    }
    if (threadIdx.x == 0) g_pool[b * T_CH + o] = sm[0] / (float)L2_OUT;
}

// ---------------- FC head ----------------
__global__ void k_fc(const float* __restrict__ fc1_w, const float* __restrict__ fc1_b,
                     const float* __restrict__ fc2_w, const float* __restrict__ fc2_b,
                     float* __restrict__ out) {
    __shared__ float z[B_SZ * H_DIM];
    int t = threadIdx.x;
    for (int i = t; i < B_SZ * H_DIM; i += 256) {
        int b = i >> 6, j = i & 63;
        float acc = fc1_b[j];
#pragma unroll
        for (int c = 0; c < T_CH; c++) acc += g_pool[b * T_CH + c] * fc1_w[c * H_DIM + j];
        z[i] = fmaxf(acc, 0.f);
    }
    __syncthreads();
    for (int i = t; i < B_SZ * NCLS; i += 256) {
        int b = i / NCLS, c = i % NCLS;
        float acc = fc2_b[c];
#pragma unroll
        for (int j = 0; j < H_DIM; j++) acc += z[b * H_DIM + j] * fc2_w[j * NCLS + c];
        out[i] = acc;
    }
}

// ---------------- launcher ----------------
extern "C" void kernel_launch(void* const* d_in, const int* in_sizes, int n_in,
                              void* d_out, int out_size) {
    const float* x      = (const float*)d_in[0];
    const float* ew     = (const float*)d_in[1];
    const float* W1     = (const float*)d_in[2];
    const float* b1     = (const float*)d_in[3];
    const float* W2     = (const float*)d_in[4];
    const float* b2     = (const float*)d_in[5];
    const float* tc1_w  = (const float*)d_in[6];
    const float* tc1_b  = (const float*)d_in[7];
    const float* bn1_g  = (const float*)d_in[8];
    const float* bn1_b  = (const float*)d_in[9];
    const float* tc2_w  = (const float*)d_in[10];
    const float* tc2_b  = (const float*)d_in[11];
    const float* bn2_g  = (const float*)d_in[12];
    const float* bn2_b  = (const float*)d_in[13];
    const float* fc1_w  = (const float*)d_in[14];
    const float* fc1_b  = (const float*)d_in[15];
    const float* fc2_w  = (const float*)d_in[16];
    const float* fc2_b  = (const float*)d_in[17];
    const int*   ei     = (const int*)d_in[18];
    float* out = (float*)d_out;

    // degree + norm (shared by both GCN layers)
    k_deg_init<<<N_NODES / 256, 256>>>();
    k_deg_add<<<N_EDGES / 256, 256>>>(ei, ew);
    k_dinv<<<N_NODES / 256, 256>>>();
    k_norm<<<N_EDGES / 256, 256>>>(ei, ew);

    // GCN layer 1
    k_gemm1<<<N_NODES / 4, 256>>>(x, W1);
    k_zero<<<N_NODES * H_DIM / 4 / 256, 256>>>();
    k_scatter<<<(N_EDGES * 16) / 256, 256>>>(ei);
    k_post<<<N_NODES * H_DIM / 256, 256>>>(b1);

    // GCN layer 2
    k_gemm2<<<N_NODES / 4, 256>>>(W2);
    k_zero<<<N_NODES * H_DIM / 4 / 256, 256>>>();
    k_scatter<<<(N_EDGES * 16) / 256, 256>>>(ei);
    k_post<<<N_NODES * H_DIM / 256, 256>>>(b2);

    // temporal conv 1 + BN stats
    k_conv1<<<dim3((L1_OUT + 7) / 8, B_SZ), 256>>>(tc1_w, tc1_b);
    k_stats<<<T_CH, 256>>>(0);

    // temporal conv 2 (BN1 applied on the fly) + BN stats
    k_conv2<<<dim3((L2_OUT + 7) / 8, B_SZ), 256>>>(tc2_w, tc2_b, bn1_g, bn1_b);
    k_stats<<<T_CH, 256>>>(1);

    // BN2 + relu + mean pool, then FC head
    k_pool<<<B_SZ * T_CH, 256>>>(bn2_g, bn2_b);
    k_fc<<<1, 256>>>(fc1_w, fc1_b, fc2_w, fc2_b, out);
}

// round 2
// speedup vs baseline: 1.5385x; 1.5385x over previous
#include <cuda_runtime.h>
#include <cuda_bf16.h>

// Problem constants (fixed shapes)
#define N_NODES 65536
#define N_EDGES 1048576
#define C_IN    22
#define H_DIM   64
#define B_SZ    16
#define L_SEQ   4096
#define T_CH    32
#define KW      3
#define L1_OUT  4098
#define L2_OUT  4100
#define NCLS    3

// ---------------- scratch ----------------
__device__ float  g_buf0[N_NODES * H_DIM];
__device__ float  g_buf1[N_NODES * H_DIM];
__device__ float  g_dinv[N_NODES];
__device__ int    g_count[N_NODES];
__device__ int    g_off[N_NODES + 1];
__device__ int    g_cursor[N_NODES];
__device__ int    g_bsum[256];
__device__ int2   g_edge[N_EDGES];      // (src, norm-as-bits), sorted by dst
__device__ float  g_y1[B_SZ * T_CH * L1_OUT];
__device__ float  g_y2[B_SZ * T_CH * L2_OUT];
__device__ double g_dstats[128];        // [which*64 + o]=sum, [which*64+32+o]=sumsq
__device__ float  g_stats[4 * T_CH];    // mean1, rstd1, mean2, rstd2
__device__ float  g_pool[B_SZ * T_CH];

// ---------------- init: deg=1 (self loop), count=0, dstats=0 ----------------
__global__ void k_init() {
    int i = blockIdx.x * blockDim.x + threadIdx.x;
    g_dinv[i] = 1.0f;
    g_count[i] = 0;
    if (i < 128) g_dstats[i] = 0.0;
}

// ---------------- degree sum + edge histogram by destination ----------------
__global__ void k_deg_hist(const int* __restrict__ ei, const float* __restrict__ ew) {
    int e = blockIdx.x * blockDim.x + threadIdx.x;
    if (e < N_EDGES) {
        int c = ei[N_EDGES + e];
        atomicAdd(&g_dinv[c], ew[e]);
        atomicAdd(&g_count[c], 1);
    }
}

__global__ void k_dinv() {
    int i = blockIdx.x * blockDim.x + threadIdx.x;
    g_dinv[i] = rsqrtf(g_dinv[i]);   // deg >= 1 always (self loop)
}

// ---------------- exclusive scan over g_count (3-phase) ----------------
__global__ void k_scan1() {
    __shared__ int s[256];
    int tid = threadIdx.x;
    int i = blockIdx.x * 256 + tid;
    int v = g_count[i];
    s[tid] = v;
    __syncthreads();
    for (int st = 1; st < 256; st <<= 1) {
        int a = (tid >= st) ? s[tid - st] : 0;
        __syncthreads();
        s[tid] += a;
        __syncthreads();
    }
    g_off[i] = s[tid] - v;
    if (tid == 255) g_bsum[blockIdx.x] = s[255];
}

__global__ void k_scan2() {
    __shared__ int s[256];
    int tid = threadIdx.x;
    int v = g_bsum[tid];
    s[tid] = v;
    __syncthreads();
    for (int st = 1; st < 256; st <<= 1) {
        int a = (tid >= st) ? s[tid - st] : 0;
        __syncthreads();
        s[tid] += a;
        __syncthreads();
    }
    g_bsum[tid] = s[tid] - v;   // exclusive block offsets
}

__global__ void k_scan3() {
    int i = blockIdx.x * 256 + threadIdx.x;
    int o = g_off[i] + g_bsum[blockIdx.x];
    g_off[i] = o;
    g_cursor[i] = o;
    if (i == 0) g_off[N_NODES] = N_EDGES;
}

// ---------------- place edges into CSR slots (norm computed here) ----------
__global__ void k_place(const int* __restrict__ ei, const float* __restrict__ ew) {
    int e = blockIdx.x * blockDim.x + threadIdx.x;
    if (e >= N_EDGES) return;
    int r = ei[e];
    int c = ei[N_EDGES + e];
    float w = g_dinv[r] * ew[e] * g_dinv[c];
    int pos = atomicAdd(&g_cursor[c], 1);
    g_edge[pos] = make_int2(r, __float_as_int(w));
}

// ---------------- x @ W1 -> buf0 (32 nodes / block) ----------------
__global__ void k_gemm1(const float* __restrict__ x, const float* __restrict__ W1) {
    __shared__ float sW[C_IN * H_DIM];
    __shared__ float sx[32 * C_IN];
    int t = threadIdx.x;
    int n0 = blockIdx.x * 32;
    for (int i = t; i < C_IN * H_DIM; i += 256) sW[i] = W1[i];
    for (int i = t; i < 32 * C_IN; i += 256) sx[i] = x[n0 * C_IN + i];
    __syncthreads();
    int f = t & 63, nb = t >> 6;
#pragma unroll
    for (int p = 0; p < 8; p++) {
        int n = p * 4 + nb;
        float acc = 0.f;
#pragma unroll
        for (int c = 0; c < C_IN; c++) acc += sx[n * C_IN + c] * sW[c * H_DIM + f];
        g_buf0[(n0 + n) * H_DIM + f] = acc;
    }
}

// ---------------- h1 @ W2 -> buf0 (reads buf1, 32 nodes / block) --------------
__global__ void k_gemm2(const float* __restrict__ W2) {
    __shared__ float sW[H_DIM * H_DIM];
    __shared__ float sh[32 * H_DIM];
    int t = threadIdx.x;
    int n0 = blockIdx.x * 32;
    for (int i = t; i < H_DIM * H_DIM; i += 256) sW[i] = W2[i];
    for (int i = t; i < 32 * H_DIM; i += 256) sh[i] = g_buf1[n0 * H_DIM + i];
    __syncthreads();
    int f = t & 63, nb = t >> 6;
#pragma unroll
    for (int p = 0; p < 8; p++) {
        int n = p * 4 + nb;
        float acc = 0.f;
#pragma unroll
        for (int c = 0; c < H_DIM; c++) acc += sh[n * H_DIM + c] * sW[c * H_DIM + f];
        g_buf0[(n0 + n) * H_DIM + f] = acc;
    }
}

// ---------------- CSR gather: buf1[n] = relu(sum_e w*buf0[src] + d^2*buf0[n] + bias)
__global__ void k_gather(const float* __restrict__ bias) {
    int warp = (blockIdx.x * blockDim.x + threadIdx.x) >> 5;
    int lane = threadIdx.x & 31;
    if (warp >= N_NODES) return;
    int beg = g_off[warp], end = g_off[warp + 1];
    const float2* __restrict__ src = (const float2*)g_buf0;
    float ax = 0.f, ay = 0.f;
    int e = beg;
    for (; e + 1 < end; e += 2) {
        int2 e0 = g_edge[e];
        int2 e1 = g_edge[e + 1];
        float2 v0 = src[(size_t)e0.x * 32 + lane];
        float2 v1 = src[(size_t)e1.x * 32 + lane];
        float w0 = __int_as_float(e0.y);
        float w1 = __int_as_float(e1.y);
        ax += w0 * v0.x + w1 * v1.x;
        ay += w0 * v0.y + w1 * v1.y;
    }
    if (e < end) {
        int2 e0 = g_edge[e];
        float2 v0 = src[(size_t)e0.x * 32 + lane];
        float w0 = __int_as_float(e0.y);
        ax += w0 * v0.x;
        ay += w0 * v0.y;
    }
    float d = g_dinv[warp];
    d = d * d;
    float2 s = src[(size_t)warp * 32 + lane];
    ax += d * s.x + bias[lane * 2];
    ay += d * s.y + bias[lane * 2 + 1];
    float2 r = make_float2(fmaxf(ax, 0.f), fmaxf(ay, 0.f));
    ((float2*)g_buf1)[(size_t)warp * 32 + lane] = r;
}

// ---------------- conv1: [B,64,L] -> y1 [B,32,L1_OUT] (32 steps / block) -----
__global__ void k_conv1(const float* __restrict__ w, const float* __restrict__ bias) {
    __shared__ float sw[192 * 33];
    __shared__ float sx[34 * 64];
    int b = blockIdx.y;
    int t0 = blockIdx.x * 32;
    int t = threadIdx.x;
    for (int j = t; j < T_CH * H_DIM * KW; j += 256) {
        int o = j / 192, ik = j % 192;
        sw[ik * 33 + o] = w[j];
    }
    for (int j = t; j < 34 * 64; j += 256) {
        int row = j >> 6, c = j & 63;
        int l = t0 + row - 2;
        sx[j] = (l >= 0 && l < L_SEQ) ? g_buf1[((b << 12) + l) * 64 + c] : 0.f;
    }
    __syncthreads();
    int o = t & 31, tr = t >> 5;
#pragma unroll
    for (int jj = 0; jj < 4; jj++) {
        int tl = tr + jj * 8;
        int tt = t0 + tl;
        if (tt >= L1_OUT) continue;
        float acc = bias[o];
#pragma unroll
        for (int k = 0; k < KW; k++)
#pragma unroll
            for (int i = 0; i < H_DIM; i++)
                acc += sx[(tl + k) * 64 + i] * sw[(i * 3 + k) * 33 + o];
        g_y1[(b * T_CH + o) * L1_OUT + tt] = acc;
    }
}

// ---------------- BN partial stats: one block per (b, o) row ----------------
__global__ void k_stats_part(int which) {
    int b = blockIdx.x >> 5, o = blockIdx.x & 31;
    const int Lout = which ? L2_OUT : L1_OUT;
    const float* p = (which ? g_y2 : g_y1) + (b * T_CH + o) * Lout;
    double s = 0.0, sq = 0.0;
    for (int i = threadIdx.x; i < Lout; i += 256) {
        float v = p[i];
        s += v;
        sq += (double)v * v;
    }
    __shared__ double ss[256], ssq[256];
    ss[threadIdx.x] = s; ssq[threadIdx.x] = sq;
    __syncthreads();
    for (int st = 128; st > 0; st >>= 1) {
        if (threadIdx.x < st) { ss[threadIdx.x] += ss[threadIdx.x + st]; ssq[threadIdx.x] += ssq[threadIdx.x + st]; }
        __syncthreads();
    }
    if (threadIdx.x == 0) {
        atomicAdd(&g_dstats[which * 64 + o], ss[0]);
        atomicAdd(&g_dstats[which * 64 + 32 + o], ssq[0]);
    }
}

__global__ void k_stats_fin(int which) {
    int o = threadIdx.x;
    const int Lout = which ? L2_OUT : L1_OUT;
    double n = (double)B_SZ * Lout;
    double m = g_dstats[which * 64 + o] / n;
    double var = g_dstats[which * 64 + 32 + o] / n - m * m;
    g_stats[which * 64 + o] = (float)m;
    g_stats[which * 64 + 32 + o] = (float)rsqrt(var + 1e-5);
}

// ---------------- conv2: reads y1 with BN1+relu on the fly -------------------
__global__ void k_conv2(const float* __restrict__ w, const float* __restrict__ bias,
                        const float* __restrict__ g1, const float* __restrict__ be1) {
    __shared__ float sw[96 * 33];
    __shared__ float sx[32 * 34];
    int b = blockIdx.y;
    int t0 = blockIdx.x * 32;
    int t = threadIdx.x;
    for (int j = t; j < T_CH * T_CH * KW; j += 256) {
        int o = j / 96, ik = j % 96;
        sw[ik * 33 + o] = w[j];
    }
    for (int j = t; j < 32 * 34; j += 256) {
        int i = j / 34, row = j % 34;
        int l = t0 + row - 2;
        float v = 0.f;
        if (l >= 0 && l < L1_OUT) {
            float m = g_stats[i], rs = g_stats[32 + i];
            float ga = g1[i] * rs;
            float bb = be1[i] - m * ga;
            v = fmaxf(g_y1[(b * T_CH + i) * L1_OUT + l] * ga + bb, 0.f);
        }
        sx[j] = v;
    }
    __syncthreads();
    int o = t & 31, tr = t >> 5;
#pragma unroll
    for (int jj = 0; jj < 4; jj++) {
        int tl = tr + jj * 8;
        int tt = t0 + tl;
        if (tt >= L2_OUT) continue;
        float acc = bias[o];
#pragma unroll
        for (int k = 0; k < KW; k++)
#pragma unroll
            for (int i = 0; i < T_CH; i++)
                acc += sx[i * 34 + tl + k] * sw[(i * 3 + k) * 33 + o];
        g_y2[(b * T_CH + o) * L2_OUT + tt] = acc;
    }
}

// ---------------- BN2 + relu + mean pool ----------------
__global__ void k_pool(const float* __restrict__ g2, const float* __restrict__ be2) {
    int b = blockIdx.x >> 5, o = blockIdx.x & 31;
    float m = g_stats[64 + o], rs = g_stats[96 + o];
    float ga = g2[o] * rs;
    float bb = be2[o] - m * ga;
    const float* y = g_y2 + (b * T_CH + o) * L2_OUT;
    float s = 0.f;
    for (int i = threadIdx.x; i < L2_OUT; i += 256) s += fmaxf(y[i] * ga + bb, 0.f);
    __shared__ float sm[256];
    sm[threadIdx.x] = s;
    __syncthreads();
    for (int st = 128; st > 0; st >>= 1) {
        if (threadIdx.x < st) sm[threadIdx.x] += sm[threadIdx.x + st];
        __syncthreads();
    }
    if (threadIdx.x == 0) g_pool[b * T_CH + o] = sm[0] / (float)L2_OUT;
}

// ---------------- FC head ----------------
__global__ void k_fc(const float* __restrict__ fc1_w, const float* __restrict__ fc1_b,
                     const float* __restrict__ fc2_w, const float* __restrict__ fc2_b,
                     float* __restrict__ out) {
    __shared__ float z[B_SZ * H_DIM];
    int t = threadIdx.x;
    for (int i = t; i < B_SZ * H_DIM; i += 256) {
        int b = i >> 6, j = i & 63;
        float acc = fc1_b[j];
#pragma unroll
        for (int c = 0; c < T_CH; c++) acc += g_pool[b * T_CH + c] * fc1_w[c * H_DIM + j];
        z[i] = fmaxf(acc, 0.f);
    }
    __syncthreads();
    for (int i = t; i < B_SZ * NCLS; i += 256) {
        int b = i / NCLS, c = i % NCLS;
        float acc = fc2_b[c];
#pragma unroll
        for (int j = 0; j < H_DIM; j++) acc += z[b * H_DIM + j] * fc2_w[j * NCLS + c];
        out[i] = acc;
    }
}

// ---------------- launcher ----------------
extern "C" void kernel_launch(void* const* d_in, const int* in_sizes, int n_in,
                              void* d_out, int out_size) {
    const float* x      = (const float*)d_in[0];
    const float* ew     = (const float*)d_in[1];
    const float* W1     = (const float*)d_in[2];
    const float* b1     = (const float*)d_in[3];
    const float* W2     = (const float*)d_in[4];
    const float* b2     = (const float*)d_in[5];
    const float* tc1_w  = (const float*)d_in[6];
    const float* tc1_b  = (const float*)d_in[7];
    const float* bn1_g  = (const float*)d_in[8];
    const float* bn1_b  = (const float*)d_in[9];
    const float* tc2_w  = (const float*)d_in[10];
    const float* tc2_b  = (const float*)d_in[11];
    const float* bn2_g  = (const float*)d_in[12];
    const float* bn2_b  = (const float*)d_in[13];
    const float* fc1_w  = (const float*)d_in[14];
    const float* fc1_b  = (const float*)d_in[15];
    const float* fc2_w  = (const float*)d_in[16];
    const float* fc2_b  = (const float*)d_in[17];
    const int*   ei     = (const int*)d_in[18];
    float* out = (float*)d_out;

    // CSR build (shared by both GCN layers)
    k_init<<<N_NODES / 256, 256>>>();
    k_deg_hist<<<N_EDGES / 256, 256>>>(ei, ew);
    k_dinv<<<N_NODES / 256, 256>>>();
    k_scan1<<<256, 256>>>();
    k_scan2<<<1, 256>>>();
    k_scan3<<<256, 256>>>();
    k_place<<<N_EDGES / 256, 256>>>(ei, ew);

    // GCN layer 1
    k_gemm1<<<N_NODES / 32, 256>>>(x, W1);
    k_gather<<<N_NODES * 32 / 256, 256>>>(b1);

    // GCN layer 2
    k_gemm2<<<N_NODES / 32, 256>>>(W2);
    k_gather<<<N_NODES * 32 / 256, 256>>>(b2);

    // temporal conv 1 + BN stats
    k_conv1<<<dim3((L1_OUT + 31) / 32, B_SZ), 256>>>(tc1_w, tc1_b);
    k_stats_part<<<B_SZ * T_CH, 256>>>(0);
    k_stats_fin<<<1, 32>>>(0);

    // temporal conv 2 + BN stats
    k_conv2<<<dim3((L2_OUT + 31) / 32, B_SZ), 256>>>(tc2_w, tc2_b, bn1_g, bn1_b);
    k_stats_part<<<B_SZ * T_CH, 256>>>(1);
    k_stats_fin<<<1, 32>>>(1);

    // BN2 + relu + pool, FC head
    k_pool<<<B_SZ * T_CH, 256>>>(bn2_g, bn2_b);
    k_fc<<<1, 256>>>(fc1_w, fc1_b, fc2_w, fc2_b, out);
}

// round 3
// speedup vs baseline: 2.0992x; 1.3644x over previous
#include <cuda_runtime.h>
#include <cuda_bf16.h>

// Problem constants (fixed shapes)
#define N_NODES 65536
#define N_EDGES 1048576
#define C_IN    22
#define H_DIM   64
#define B_SZ    16
#define L_SEQ   4096
#define T_CH    32
#define KW      3
#define L1_OUT  4098
#define L2_OUT  4100
#define NCLS    3

// ---------------- scratch ----------------
__device__ float  g_aggx[N_NODES * C_IN];   // aggregated x (layer-1 pre-GEMM)
__device__ float  g_buf0[N_NODES * H_DIM];  // layer-2 pre-aggregation features
__device__ float  g_buf1[N_NODES * H_DIM];  // activated hidden
__device__ float  g_dinv[N_NODES];
__device__ int    g_count[N_NODES];
__device__ int    g_off[N_NODES + 1];
__device__ int    g_cursor[N_NODES];
__device__ int    g_bsum[256];
__device__ int2   g_edge[N_EDGES];          // (src, norm-as-bits), sorted by dst
__device__ float  g_y1[B_SZ * T_CH * L1_OUT];
__device__ float  g_y2[B_SZ * T_CH * L2_OUT];
__device__ double g_dstats[128];
__device__ float  g_stats[4 * T_CH];        // mean1, rstd1, mean2, rstd2
__device__ float  g_pool[B_SZ * T_CH];

// ---------------- init ----------------
__global__ void k_init() {
    int i = blockIdx.x * blockDim.x + threadIdx.x;
    g_dinv[i] = 1.0f;     // self-loop weight
    g_count[i] = 0;
    if (i < 128) g_dstats[i] = 0.0;
}

__global__ void k_deg_hist(const int* __restrict__ ei, const float* __restrict__ ew) {
    int e = blockIdx.x * blockDim.x + threadIdx.x;
    if (e < N_EDGES) {
        int c = ei[N_EDGES + e];
        atomicAdd(&g_dinv[c], ew[e]);
        atomicAdd(&g_count[c], 1);
    }
}

// ---------------- scan phase 1 (+ dinv finalize folded in) ----------------
__global__ void k_scan1() {
    __shared__ int s[256];
    int tid = threadIdx.x;
    int i = blockIdx.x * 256 + tid;
    g_dinv[i] = rsqrtf(g_dinv[i]);   // deg >= 1 always
    int v = g_count[i];
    s[tid] = v;
    __syncthreads();
    for (int st = 1; st < 256; st <<= 1) {
        int a = (tid >= st) ? s[tid - st] : 0;
        __syncthreads();
        s[tid] += a;
        __syncthreads();
    }
    g_off[i] = s[tid] - v;
    if (tid == 255) g_bsum[blockIdx.x] = s[255];
}

__global__ void k_scan2() {
    __shared__ int s[256];
    int tid = threadIdx.x;
    int v = g_bsum[tid];
    s[tid] = v;
    __syncthreads();
    for (int st = 1; st < 256; st <<= 1) {
        int a = (tid >= st) ? s[tid - st] : 0;
        __syncthreads();
        s[tid] += a;
        __syncthreads();
    }
    g_bsum[tid] = s[tid] - v;
}

__global__ void k_scan3() {
    int i = blockIdx.x * 256 + threadIdx.x;
    int o = g_off[i] + g_bsum[blockIdx.x];
    g_off[i] = o;
    g_cursor[i] = o;
    if (i == 0) g_off[N_NODES] = N_EDGES;
}

__global__ void k_place(const int* __restrict__ ei, const float* __restrict__ ew) {
    int e = blockIdx.x * blockDim.x + threadIdx.x;
    if (e >= N_EDGES) return;
    int r = ei[e];
    int c = ei[N_EDGES + e];
    float w = g_dinv[r] * ew[e] * g_dinv[c];
    int pos = atomicAdd(&g_cursor[c], 1);
    g_edge[pos] = make_int2(r, __float_as_int(w));
}

// ---------------- layer-1 aggregation on raw x (22 dims) ----------------
__global__ void k_gather22(const float* __restrict__ x) {
    int warp = (blockIdx.x * blockDim.x + threadIdx.x) >> 5;
    int lane = threadIdx.x & 31;
    if (warp >= N_NODES) return;
    bool act = lane < C_IN;
    int beg = g_off[warp], end = g_off[warp + 1];
    float a = 0.f;
    int e = beg;
    for (; e + 1 < end; e += 2) {
        int2 e0 = g_edge[e];
        int2 e1 = g_edge[e + 1];
        float w0 = __int_as_float(e0.y);
        float w1 = __int_as_float(e1.y);
        if (act) {
            a += w0 * x[(size_t)e0.x * C_IN + lane];
            a += w1 * x[(size_t)e1.x * C_IN + lane];
        }
    }
    if (e < end) {
        int2 e0 = g_edge[e];
        float w0 = __int_as_float(e0.y);
        if (act) a += w0 * x[(size_t)e0.x * C_IN + lane];
    }
    float d = g_dinv[warp];
    d = d * d;
    if (act) {
        a += d * x[(size_t)warp * C_IN + lane];
        g_aggx[(size_t)warp * C_IN + lane] = a;
    }
}

// ---------------- aggx @ W1 + b1, relu -> buf1 (32 nodes/block) ----------
__global__ void k_gemm1(const float* __restrict__ W1, const float* __restrict__ b1) {
    __shared__ float sW[C_IN * H_DIM];
    __shared__ float sx[32 * C_IN];
    int t = threadIdx.x;
    int n0 = blockIdx.x * 32;
    for (int i = t; i < C_IN * H_DIM; i += 256) sW[i] = W1[i];
    for (int i = t; i < 32 * C_IN; i += 256) sx[i] = g_aggx[n0 * C_IN + i];
    __syncthreads();
    int f = t & 63, nb = t >> 6;
    float bias = b1[f];
#pragma unroll
    for (int p = 0; p < 8; p++) {
        int n = p * 4 + nb;
        float acc = bias;
#pragma unroll
        for (int c = 0; c < C_IN; c++) acc += sx[n * C_IN + c] * sW[c * H_DIM + f];
        g_buf1[(n0 + n) * H_DIM + f] = fmaxf(acc, 0.f);
    }
}

// ---------------- buf1 @ W2 -> buf0 (32 nodes/block) ----------------
__global__ void k_gemm2(const float* __restrict__ W2) {
    __shared__ float sW[H_DIM * H_DIM];
    __shared__ float sh[32 * H_DIM];
    int t = threadIdx.x;
    int n0 = blockIdx.x * 32;
    for (int i = t; i < H_DIM * H_DIM; i += 256) sW[i] = W2[i];
    for (int i = t; i < 32 * H_DIM; i += 256) sh[i] = g_buf1[n0 * H_DIM + i];
    __syncthreads();
    int f = t & 63, nb = t >> 6;
#pragma unroll
    for (int p = 0; p < 8; p++) {
        int n = p * 4 + nb;
        float acc = 0.f;
#pragma unroll
        for (int c = 0; c < H_DIM; c++) acc += sh[n * H_DIM + c] * sW[c * H_DIM + f];
        g_buf0[(n0 + n) * H_DIM + f] = acc;
    }
}

// ---------------- layer-2 CSR gather (64 dims) + bias + relu -> buf1 -------
__global__ void k_gather64(const float* __restrict__ bias) {
    int warp = (blockIdx.x * blockDim.x + threadIdx.x) >> 5;
    int lane = threadIdx.x & 31;
    if (warp >= N_NODES) return;
    int beg = g_off[warp], end = g_off[warp + 1];
    const float2* __restrict__ src = (const float2*)g_buf0;
    float ax = 0.f, ay = 0.f;
    int e = beg;
    for (; e + 1 < end; e += 2) {
        int2 e0 = g_edge[e];
        int2 e1 = g_edge[e + 1];
        float2 v0 = src[(size_t)e0.x * 32 + lane];
        float2 v1 = src[(size_t)e1.x * 32 + lane];
        float w0 = __int_as_float(e0.y);
        float w1 = __int_as_float(e1.y);
        ax += w0 * v0.x + w1 * v1.x;
        ay += w0 * v0.y + w1 * v1.y;
    }
    if (e < end) {
        int2 e0 = g_edge[e];
        float2 v0 = src[(size_t)e0.x * 32 + lane];
        float w0 = __int_as_float(e0.y);
        ax += w0 * v0.x;
        ay += w0 * v0.y;
    }
    float d = g_dinv[warp];
    d = d * d;
    float2 s = src[(size_t)warp * 32 + lane];
    ax += d * s.x + bias[lane * 2];
    ay += d * s.y + bias[lane * 2 + 1];
    ((float2*)g_buf1)[(size_t)warp * 32 + lane] =
        make_float2(fmaxf(ax, 0.f), fmaxf(ay, 0.f));
}

// ---------------- conv1: [B,64,L] -> y1 [B,32,L1_OUT], 64 steps/block -------
// Thread tiling: 2 output channels x 4 consecutive timesteps per thread.
__global__ void k_conv1(const float* __restrict__ w, const float* __restrict__ bias) {
    __shared__ __align__(8) float sw[H_DIM * KW * 34];   // sw[(i*3+k)*34 + o]
    __shared__ float sx[66 * 64];                        // rows t0-2 .. t0+63
    int b = blockIdx.y;
    int t0 = blockIdx.x * 64;
    int t = threadIdx.x;
    for (int j = t; j < T_CH * H_DIM * KW; j += 256) {
        int o = j / (H_DIM * KW), ik = j % (H_DIM * KW);
        sw[ik * 34 + o] = w[j];
    }
    for (int j = t; j < 66 * 64; j += 256) {
        int row = j >> 6, c = j & 63;
        int l = t0 + row - 2;
        sx[j] = (l >= 0 && l < L_SEQ) ? g_buf1[((b << 12) + l) * 64 + c] : 0.f;
    }
    __syncthreads();
    int to = t & 15, tq = t >> 4;
    int o2 = to * 2;
    float acc0[4], acc1[4];
    float b0 = bias[o2], b1v = bias[o2 + 1];
#pragma unroll
    for (int j = 0; j < 4; j++) { acc0[j] = b0; acc1[j] = b1v; }
#pragma unroll
    for (int i = 0; i < H_DIM; i++) {
        float xr[6];
#pragma unroll
        for (int r = 0; r < 6; r++) xr[r] = sx[(4 * tq + r) * 64 + i];
#pragma unroll
        for (int k = 0; k < KW; k++) {
            float2 wv = *(const float2*)&sw[(i * 3 + k) * 34 + o2];
#pragma unroll
            for (int j = 0; j < 4; j++) {
                acc0[j] += xr[j + k] * wv.x;
                acc1[j] += xr[j + k] * wv.y;
            }
        }
    }
    int tb = t0 + 4 * tq;
    float* p0 = &g_y1[(b * T_CH + o2) * L1_OUT + tb];
    float* p1 = &g_y1[(b * T_CH + o2 + 1) * L1_OUT + tb];
    if (tb + 3 < L1_OUT) {
        ((float2*)p0)[0] = make_float2(acc0[0], acc0[1]);
        ((float2*)p0)[1] = make_float2(acc0[2], acc0[3]);
        ((float2*)p1)[0] = make_float2(acc1[0], acc1[1]);
        ((float2*)p1)[1] = make_float2(acc1[2], acc1[3]);
    } else {
#pragma unroll
        for (int j = 0; j < 4; j++)
            if (tb + j < L1_OUT) { p0[j] = acc0[j]; p1[j] = acc1[j]; }
    }
}

// ---------------- BN partial stats ----------------
__global__ void k_stats_part(int which) {
    int b = blockIdx.x >> 5, o = blockIdx.x & 31;
    const int Lout = which ? L2_OUT : L1_OUT;
    const float* p = (which ? g_y2 : g_y1) + (b * T_CH + o) * Lout;
    double s = 0.0, sq = 0.0;
    for (int i = threadIdx.x; i < Lout; i += 256) {
        float v = p[i];
        s += v;
        sq += (double)v * v;
    }
    __shared__ double ss[256], ssq[256];
    ss[threadIdx.x] = s; ssq[threadIdx.x] = sq;
    __syncthreads();
    for (int st = 128; st > 0; st >>= 1) {
        if (threadIdx.x < st) { ss[threadIdx.x] += ss[threadIdx.x + st]; ssq[threadIdx.x] += ssq[threadIdx.x + st]; }
        __syncthreads();
    }
    if (threadIdx.x == 0) {
        atomicAdd(&g_dstats[which * 64 + o], ss[0]);
        atomicAdd(&g_dstats[which * 64 + 32 + o], ssq[0]);
    }
}

__global__ void k_stats_fin(int which) {
    int o = threadIdx.x;
    const int Lout = which ? L2_OUT : L1_OUT;
    double n = (double)B_SZ * Lout;
    double m = g_dstats[which * 64 + o] / n;
    double var = g_dstats[which * 64 + 32 + o] / n - m * m;
    g_stats[which * 64 + o] = (float)m;
    g_stats[which * 64 + 32 + o] = (float)rsqrt(var + 1e-5);
}

// ---------------- conv2 (BN1+relu on the fly), 64 steps/block ----------------
__global__ void k_conv2(const float* __restrict__ w, const float* __restrict__ bias,
                        const float* __restrict__ g1, const float* __restrict__ be1) {
    __shared__ __align__(8) float sw[T_CH * KW * 34];    // sw[(i*3+k)*34 + o]
    __shared__ float sx[66 * 33];                        // sx[row*33 + i]
    int b = blockIdx.y;
    int t0 = blockIdx.x * 64;
    int t = threadIdx.x;
    for (int j = t; j < T_CH * T_CH * KW; j += 256) {
        int o = j / (T_CH * KW), ik = j % (T_CH * KW);
        sw[ik * 34 + o] = w[j];
    }
    for (int j = t; j < 32 * 66; j += 256) {
        int i = j / 66, row = j % 66;
        int l = t0 + row - 2;
        float v = 0.f;
        if (l >= 0 && l < L1_OUT) {
            float m = g_stats[i], rs = g_stats[32 + i];
            float ga = g1[i] * rs;
            float bb = be1[i] - m * ga;
            v = fmaxf(g_y1[(b * T_CH + i) * L1_OUT + l] * ga + bb, 0.f);
        }
        sx[row * 33 + i] = v;
    }
    __syncthreads();
    int to = t & 15, tq = t >> 4;
    int o2 = to * 2;
    float acc0[4], acc1[4];
    float b0 = bias[o2], b1v = bias[o2 + 1];
#pragma unroll
    for (int j = 0; j < 4; j++) { acc0[j] = b0; acc1[j] = b1v; }
#pragma unroll
    for (int i = 0; i < T_CH; i++) {
        float xr[6];
#pragma unroll
        for (int r = 0; r < 6; r++) xr[r] = sx[(4 * tq + r) * 33 + i];
#pragma unroll
        for (int k = 0; k < KW; k++) {
            float2 wv = *(const float2*)&sw[(i * 3 + k) * 34 + o2];
#pragma unroll
            for (int j = 0; j < 4; j++) {
                acc0[j] += xr[j + k] * wv.x;
                acc1[j] += xr[j + k] * wv.y;
            }
        }
    }
    int tb = t0 + 4 * tq;
    float* p0 = &g_y2[(b * T_CH + o2) * L2_OUT + tb];
    float* p1 = &g_y2[(b * T_CH + o2 + 1) * L2_OUT + tb];
    if (tb + 3 < L2_OUT) {
        ((float2*)p0)[0] = make_float2(acc0[0], acc0[1]);
        ((float2*)p0)[1] = make_float2(acc0[2], acc0[3]);
        ((float2*)p1)[0] = make_float2(acc1[0], acc1[1]);
        ((float2*)p1)[1] = make_float2(acc1[2], acc1[3]);
    } else {
#pragma unroll
        for (int j = 0; j < 4; j++)
            if (tb + j < L2_OUT) { p0[j] = acc0[j]; p1[j] = acc1[j]; }
    }
}

// ---------------- BN2 + relu + mean pool ----------------
__global__ void k_pool(const float* __restrict__ g2, const float* __restrict__ be2) {
    int b = blockIdx.x >> 5, o = blockIdx.x & 31;
    float m = g_stats[64 + o], rs = g_stats[96 + o];
    float ga = g2[o] * rs;
    float bb = be2[o] - m * ga;
    const float* y = g_y2 + (b * T_CH + o) * L2_OUT;
    float s = 0.f;
    for (int i = threadIdx.x; i < L2_OUT; i += 256) s += fmaxf(y[i] * ga + bb, 0.f);
    __shared__ float sm[256];
    sm[threadIdx.x] = s;
    __syncthreads();
    for (int st = 128; st > 0; st >>= 1) {
        if (threadIdx.x < st) sm[threadIdx.x] += sm[threadIdx.x + st];
        __syncthreads();
    }
    if (threadIdx.x == 0) g_pool[b * T_CH + o] = sm[0] / (float)L2_OUT;
}

// ---------------- FC head ----------------
__global__ void k_fc(const float* __restrict__ fc1_w, const float* __restrict__ fc1_b,
                     const float* __restrict__ fc2_w, const float* __restrict__ fc2_b,
                     float* __restrict__ out) {
    __shared__ float z[B_SZ * H_DIM];
    int t = threadIdx.x;
    for (int i = t; i < B_SZ * H_DIM; i += 256) {
        int b = i >> 6, j = i & 63;
        float acc = fc1_b[j];
#pragma unroll
        for (int c = 0; c < T_CH; c++) acc += g_pool[b * T_CH + c] * fc1_w[c * H_DIM + j];
        z[i] = fmaxf(acc, 0.f);
    }
    __syncthreads();
    for (int i = t; i < B_SZ * NCLS; i += 256) {
        int b = i / NCLS, c = i % NCLS;
        float acc = fc2_b[c];
#pragma unroll
        for (int j = 0; j < H_DIM; j++) acc += z[b * H_DIM + j] * fc2_w[j * NCLS + c];
        out[i] = acc;
    }
}

// ---------------- launcher ----------------
extern "C" void kernel_launch(void* const* d_in, const int* in_sizes, int n_in,
                              void* d_out, int out_size) {
    const float* x      = (const float*)d_in[0];
    const float* ew     = (const float*)d_in[1];
    const float* W1     = (const float*)d_in[2];
    const float* b1     = (const float*)d_in[3];
    const float* W2     = (const float*)d_in[4];
    const float* b2     = (const float*)d_in[5];
    const float* tc1_w  = (const float*)d_in[6];
    const float* tc1_b  = (const float*)d_in[7];
    const float* bn1_g  = (const float*)d_in[8];
    const float* bn1_b  = (const float*)d_in[9];
    const float* tc2_w  = (const float*)d_in[10];
    const float* tc2_b  = (const float*)d_in[11];
    const float* bn2_g  = (const float*)d_in[12];
    const float* bn2_b  = (const float*)d_in[13];
    const float* fc1_w  = (const float*)d_in[14];
    const float* fc1_b  = (const float*)d_in[15];
    const float* fc2_w  = (const float*)d_in[16];
    const float* fc2_b  = (const float*)d_in[17];
    const int*   ei     = (const int*)d_in[18];
    float* out = (float*)d_out;

    // CSR build (shared by both GCN layers)
    k_init<<<N_NODES / 256, 256>>>();
    k_deg_hist<<<N_EDGES / 256, 256>>>(ei, ew);
    k_scan1<<<256, 256>>>();
    k_scan2<<<1, 256>>>();
    k_scan3<<<256, 256>>>();
    k_place<<<N_EDGES / 256, 256>>>(ei, ew);

    // GCN layer 1: aggregate x (22-dim) then transform
    k_gather22<<<N_NODES * 32 / 256, 256>>>(x);
    k_gemm1<<<N_NODES / 32, 256>>>(W1, b1);

    // GCN layer 2: transform then aggregate
    k_gemm2<<<N_NODES / 32, 256>>>(W2);
    k_gather64<<<N_NODES * 32 / 256, 256>>>(b2);

    // temporal conv 1 + BN stats
    k_conv1<<<dim3((L1_OUT + 63) / 64, B_SZ), 256>>>(tc1_w, tc1_b);
    k_stats_part<<<B_SZ * T_CH, 256>>>(0);
    k_stats_fin<<<1, 32>>>(0);

    // temporal conv 2 + BN stats
    k_conv2<<<dim3((L2_OUT + 63) / 64, B_SZ), 256>>>(tc2_w, tc2_b, bn1_g, bn1_b);
    k_stats_part<<<B_SZ * T_CH, 256>>>(1);
    k_stats_fin<<<1, 32>>>(1);

    // BN2 + relu + pool, FC head
    k_pool<<<B_SZ * T_CH, 256>>>(bn2_g, bn2_b);
    k_fc<<<1, 256>>>(fc1_w, fc1_b, fc2_w, fc2_b, out);
}

// round 4
// speedup vs baseline: 2.3722x; 1.1300x over previous
#include <cuda_runtime.h>
#include <cuda_fp16.h>

// Problem constants (fixed shapes)
#define N_NODES 65536
#define N_EDGES 1048576
#define C_IN    22
#define H_DIM   64
#define B_SZ    16
#define L_SEQ   4096
#define T_CH    32
#define KW      3
#define L1_OUT  4098
#define L2_OUT  4100
#define NCLS    3
#define EPSF    1e-5

// ---------------- scratch ----------------
__device__ float   g_aggx[N_NODES * C_IN];   // aggregated x (layer-1 pre-GEMM)
__device__ float   g_buf1[N_NODES * H_DIM];  // activated hidden (fp32)
__device__ __half  g_hbuf[N_NODES * H_DIM];  // layer-2 pre-aggregation (fp16)
__device__ float   g_dinv[N_NODES];
__device__ int     g_count[N_NODES];
__device__ int     g_off[N_NODES + 1];
__device__ int     g_cursor[N_NODES];
__device__ int     g_bsum[256];
__device__ int2    g_edge[N_EDGES];          // (src, norm-as-bits), sorted by dst
__device__ float   g_y1[B_SZ * T_CH * L1_OUT];
__device__ float   g_y2[B_SZ * T_CH * L2_OUT];
__device__ double  g_dstats[128];            // sums/sumsqs for BN1 (0..63) / BN2 (64..127)
__device__ float   g_pool[B_SZ * T_CH];

// ---------------- init ----------------
__global__ void k_init() {
    int i = blockIdx.x * blockDim.x + threadIdx.x;
    g_dinv[i] = 1.0f;     // self-loop weight
    g_count[i] = 0;
    if (i < 128) g_dstats[i] = 0.0;
}

__global__ void k_deg_hist(const int* __restrict__ ei, const float* __restrict__ ew) {
    int e = blockIdx.x * blockDim.x + threadIdx.x;
    if (e < N_EDGES) {
        int c = ei[N_EDGES + e];
        atomicAdd(&g_dinv[c], ew[e]);
        atomicAdd(&g_count[c], 1);
    }
}

// ---------------- scan phase 1 (+ dinv finalize) ----------------
__global__ void k_scan1() {
    __shared__ int s[256];
    int tid = threadIdx.x;
    int i = blockIdx.x * 256 + tid;
    g_dinv[i] = rsqrtf(g_dinv[i]);
    int v = g_count[i];
    s[tid] = v;
    __syncthreads();
    for (int st = 1; st < 256; st <<= 1) {
        int a = (tid >= st) ? s[tid - st] : 0;
        __syncthreads();
        s[tid] += a;
        __syncthreads();
    }
    g_off[i] = s[tid] - v;
    if (tid == 255) g_bsum[blockIdx.x] = s[255];
}

// ---------------- scan phases 2+3 merged: each block reduces bsum prefix ----
__global__ void k_scan23() {
    __shared__ int s[256];
    int tid = threadIdx.x;
    s[tid] = (tid < (int)blockIdx.x) ? g_bsum[tid] : 0;
    __syncthreads();
    for (int st = 128; st > 0; st >>= 1) {
        if (tid < st) s[tid] += s[tid + st];
        __syncthreads();
    }
    int i = blockIdx.x * 256 + tid;
    int o = g_off[i] + s[0];
    g_off[i] = o;
    g_cursor[i] = o;
    if (i == 0) g_off[N_NODES] = N_EDGES;
}

__global__ void k_place(const int* __restrict__ ei, const float* __restrict__ ew) {
    int e = blockIdx.x * blockDim.x + threadIdx.x;
    if (e >= N_EDGES) return;
    int r = ei[e];
    int c = ei[N_EDGES + e];
    float w = g_dinv[r] * ew[e] * g_dinv[c];
    int pos = atomicAdd(&g_cursor[c], 1);
    g_edge[pos] = make_int2(r, __float_as_int(w));
}

// ---------------- layer-1 aggregation on raw x (22 dims) ----------------
__global__ void k_gather22(const float* __restrict__ x) {
    int warp = (blockIdx.x * blockDim.x + threadIdx.x) >> 5;
    int lane = threadIdx.x & 31;
    if (warp >= N_NODES) return;
    bool act = lane < C_IN;
    int beg = g_off[warp], end = g_off[warp + 1];
    float a = 0.f;
    int e = beg;
    for (; e + 1 < end; e += 2) {
        int2 e0 = g_edge[e];
        int2 e1 = g_edge[e + 1];
        float w0 = __int_as_float(e0.y);
        float w1 = __int_as_float(e1.y);
        if (act) {
            a += w0 * x[(size_t)e0.x * C_IN + lane];
            a += w1 * x[(size_t)e1.x * C_IN + lane];
        }
    }
    if (e < end) {
        int2 e0 = g_edge[e];
        float w0 = __int_as_float(e0.y);
        if (act) a += w0 * x[(size_t)e0.x * C_IN + lane];
    }
    float d = g_dinv[warp];
    d = d * d;
    if (act) {
        a += d * x[(size_t)warp * C_IN + lane];
        g_aggx[(size_t)warp * C_IN + lane] = a;
    }
}

// ---------------- aggx @ W1 + b1, relu -> buf1 (32 nodes/block) ----------
__global__ void k_gemm1(const float* __restrict__ W1, const float* __restrict__ b1) {
    __shared__ float sW[C_IN * H_DIM];
    __shared__ float sx[32 * C_IN];
    int t = threadIdx.x;
    int n0 = blockIdx.x * 32;
    for (int i = t; i < C_IN * H_DIM; i += 256) sW[i] = W1[i];
    for (int i = t; i < 32 * C_IN; i += 256) sx[i] = g_aggx[n0 * C_IN + i];
    __syncthreads();
    int f = t & 63, nb = t >> 6;
    float bias = b1[f];
#pragma unroll
    for (int p = 0; p < 8; p++) {
        int n = p * 4 + nb;
        float acc = bias;
#pragma unroll
        for (int c = 0; c < C_IN; c++) acc += sx[n * C_IN + c] * sW[c * H_DIM + f];
        g_buf1[(n0 + n) * H_DIM + f] = fmaxf(acc, 0.f);
    }
}

// ---------------- buf1 @ W2 -> hbuf (fp16, 32 nodes/block) ----------------
__global__ void k_gemm2(const float* __restrict__ W2) {
    __shared__ float sW[H_DIM * H_DIM];
    __shared__ float sh[32 * H_DIM];
    int t = threadIdx.x;
    int n0 = blockIdx.x * 32;
    for (int i = t; i < H_DIM * H_DIM; i += 256) sW[i] = W2[i];
    for (int i = t; i < 32 * H_DIM; i += 256) sh[i] = g_buf1[n0 * H_DIM + i];
    __syncthreads();
    int f = t & 63, nb = t >> 6;
#pragma unroll
    for (int p = 0; p < 8; p++) {
        int n = p * 4 + nb;
        float acc = 0.f;
#pragma unroll
        for (int c = 0; c < H_DIM; c++) acc += sh[n * H_DIM + c] * sW[c * H_DIM + f];
        g_hbuf[(n0 + n) * H_DIM + f] = __float2half(acc);
    }
}

// ---------------- layer-2 CSR gather (fp16 src) + bias + relu -> buf1 -------
__global__ void k_gather64(const float* __restrict__ bias) {
    int warp = (blockIdx.x * blockDim.x + threadIdx.x) >> 5;
    int lane = threadIdx.x & 31;
    if (warp >= N_NODES) return;
    int beg = g_off[warp], end = g_off[warp + 1];
    const __half2* __restrict__ src = (const __half2*)g_hbuf;
    float ax = 0.f, ay = 0.f;
    int e = beg;
    for (; e + 1 < end; e += 2) {
        int2 e0 = g_edge[e];
        int2 e1 = g_edge[e + 1];
        float2 v0 = __half22float2(src[(size_t)e0.x * 32 + lane]);
        float2 v1 = __half22float2(src[(size_t)e1.x * 32 + lane]);
        float w0 = __int_as_float(e0.y);
        float w1 = __int_as_float(e1.y);
        ax += w0 * v0.x + w1 * v1.x;
        ay += w0 * v0.y + w1 * v1.y;
    }
    if (e < end) {
        int2 e0 = g_edge[e];
        float2 v0 = __half22float2(src[(size_t)e0.x * 32 + lane]);
        float w0 = __int_as_float(e0.y);
        ax += w0 * v0.x;
        ay += w0 * v0.y;
    }
    float d = g_dinv[warp];
    d = d * d;
    float2 s = __half22float2(src[(size_t)warp * 32 + lane]);
    ax += d * s.x + bias[lane * 2];
    ay += d * s.y + bias[lane * 2 + 1];
    ((float2*)g_buf1)[(size_t)warp * 32 + lane] =
        make_float2(fmaxf(ax, 0.f), fmaxf(ay, 0.f));
}

// ---------------- conv1 + fused BN1 stat accumulation ----------------
__global__ void k_conv1(const float* __restrict__ w, const float* __restrict__ bias) {
    __shared__ __align__(8) float sw[H_DIM * KW * 34];   // sw[(i*3+k)*34 + o]
    __shared__ float sx[66 * 64];
    __shared__ float s_sum[T_CH], s_sq[T_CH];
    int b = blockIdx.y;
    int t0 = blockIdx.x * 64;
    int t = threadIdx.x;
    if (t < T_CH) { s_sum[t] = 0.f; s_sq[t] = 0.f; }
    for (int j = t; j < T_CH * H_DIM * KW; j += 256) {
        int o = j / (H_DIM * KW), ik = j % (H_DIM * KW);
        sw[ik * 34 + o] = w[j];
    }
    for (int j = t; j < 66 * 64; j += 256) {
        int row = j >> 6, c = j & 63;
        int l = t0 + row - 2;
        sx[j] = (l >= 0 && l < L_SEQ) ? g_buf1[((b << 12) + l) * 64 + c] : 0.f;
    }
    __syncthreads();
    int to = t & 15, tq = t >> 4;
    int o2 = to * 2;
    float acc0[4], acc1[4];
    float b0 = bias[o2], b1v = bias[o2 + 1];
#pragma unroll
    for (int j = 0; j < 4; j++) { acc0[j] = b0; acc1[j] = b1v; }
#pragma unroll
    for (int i = 0; i < H_DIM; i++) {
        float xr[6];
#pragma unroll
        for (int r = 0; r < 6; r++) xr[r] = sx[(4 * tq + r) * 64 + i];
#pragma unroll
        for (int k = 0; k < KW; k++) {
            float2 wv = *(const float2*)&sw[(i * 3 + k) * 34 + o2];
#pragma unroll
            for (int j = 0; j < 4; j++) {
                acc0[j] += xr[j + k] * wv.x;
                acc1[j] += xr[j + k] * wv.y;
            }
        }
    }
    int tb = t0 + 4 * tq;
    float* p0 = &g_y1[(b * T_CH + o2) * L1_OUT + tb];
    float* p1 = &g_y1[(b * T_CH + o2 + 1) * L1_OUT + tb];
    float s0 = 0.f, q0 = 0.f, s1 = 0.f, q1 = 0.f;
    if (tb + 3 < L1_OUT) {
        ((float2*)p0)[0] = make_float2(acc0[0], acc0[1]);
        ((float2*)p0)[1] = make_float2(acc0[2], acc0[3]);
        ((float2*)p1)[0] = make_float2(acc1[0], acc1[1]);
        ((float2*)p1)[1] = make_float2(acc1[2], acc1[3]);
#pragma unroll
        for (int j = 0; j < 4; j++) {
            s0 += acc0[j]; q0 += acc0[j] * acc0[j];
            s1 += acc1[j]; q1 += acc1[j] * acc1[j];
        }
    } else {
#pragma unroll
        for (int j = 0; j < 4; j++)
            if (tb + j < L1_OUT) {
                p0[j] = acc0[j]; p1[j] = acc1[j];
                s0 += acc0[j]; q0 += acc0[j] * acc0[j];
                s1 += acc1[j]; q1 += acc1[j] * acc1[j];
            }
    }
    atomicAdd(&s_sum[o2], s0);     atomicAdd(&s_sq[o2], q0);
    atomicAdd(&s_sum[o2 + 1], s1); atomicAdd(&s_sq[o2 + 1], q1);
    __syncthreads();
    if (t < T_CH) {
        atomicAdd(&g_dstats[t], (double)s_sum[t]);
        atomicAdd(&g_dstats[32 + t], (double)s_sq[t]);
    }
}

// ---------------- conv2 (BN1 finalized inline) + fused BN2 stats ------------
__global__ void k_conv2(const float* __restrict__ w, const float* __restrict__ bias,
                        const float* __restrict__ g1, const float* __restrict__ be1) {
    __shared__ __align__(8) float sw[T_CH * KW * 34];
    __shared__ float sx[66 * 33];
    __shared__ float s_ga[T_CH], s_bb[T_CH];
    __shared__ float s_sum[T_CH], s_sq[T_CH];
    int b = blockIdx.y;
    int t0 = blockIdx.x * 64;
    int t = threadIdx.x;
    if (t < T_CH) {
        double n = (double)B_SZ * L1_OUT;
        double m = g_dstats[t] / n;
        double var = g_dstats[32 + t] / n - m * m;
        float rs = (float)rsqrt(var + EPSF);
        float ga = g1[t] * rs;
        s_ga[t] = ga;
        s_bb[t] = be1[t] - (float)m * ga;
        s_sum[t] = 0.f; s_sq[t] = 0.f;
    }
    for (int j = t; j < T_CH * T_CH * KW; j += 256) {
        int o = j / (T_CH * KW), ik = j % (T_CH * KW);
        sw[ik * 34 + o] = w[j];
    }
    __syncthreads();
    for (int j = t; j < 32 * 66; j += 256) {
        int i = j / 66, row = j % 66;
        int l = t0 + row - 2;
        float v = 0.f;
        if (l >= 0 && l < L1_OUT)
            v = fmaxf(g_y1[(b * T_CH + i) * L1_OUT + l] * s_ga[i] + s_bb[i], 0.f);
        sx[row * 33 + i] = v;
    }
    __syncthreads();
    int to = t & 15, tq = t >> 4;
    int o2 = to * 2;
    float acc0[4], acc1[4];
    float b0 = bias[o2], b1v = bias[o2 + 1];
#pragma unroll
    for (int j = 0; j < 4; j++) { acc0[j] = b0; acc1[j] = b1v; }
#pragma unroll
    for (int i = 0; i < T_CH; i++) {
        float xr[6];
#pragma unroll
        for (int r = 0; r < 6; r++) xr[r] = sx[(4 * tq + r) * 33 + i];
#pragma unroll
        for (int k = 0; k < KW; k++) {
            float2 wv = *(const float2*)&sw[(i * 3 + k) * 34 + o2];
#pragma unroll
            for (int j = 0; j < 4; j++) {
                acc0[j] += xr[j + k] * wv.x;
                acc1[j] += xr[j + k] * wv.y;
            }
        }
    }
    int tb = t0 + 4 * tq;
    float* p0 = &g_y2[(b * T_CH + o2) * L2_OUT + tb];
    float* p1 = &g_y2[(b * T_CH + o2 + 1) * L2_OUT + tb];
    float s0 = 0.f, q0 = 0.f, s1 = 0.f, q1 = 0.f;
    if (tb + 3 < L2_OUT) {
        ((float2*)p0)[0] = make_float2(acc0[0], acc0[1]);
        ((float2*)p0)[1] = make_float2(acc0[2], acc0[3]);
        ((float2*)p1)[0] = make_float2(acc1[0], acc1[1]);
        ((float2*)p1)[1] = make_float2(acc1[2], acc1[3]);
#pragma unroll
        for (int j = 0; j < 4; j++) {
            s0 += acc0[j]; q0 += acc0[j] * acc0[j];
            s1 += acc1[j]; q1 += acc1[j] * acc1[j];
        }
    } else {
#pragma unroll
        for (int j = 0; j < 4; j++)
            if (tb + j < L2_OUT) {
                p0[j] = acc0[j]; p1[j] = acc1[j];
                s0 += acc0[j]; q0 += acc0[j] * acc0[j];
                s1 += acc1[j]; q1 += acc1[j] * acc1[j];
            }
    }
    atomicAdd(&s_sum[o2], s0);     atomicAdd(&s_sq[o2], q0);
    atomicAdd(&s_sum[o2 + 1], s1); atomicAdd(&s_sq[o2 + 1], q1);
    __syncthreads();
    if (t < T_CH) {
        atomicAdd(&g_dstats[64 + t], (double)s_sum[t]);
        atomicAdd(&g_dstats[96 + t], (double)s_sq[t]);
    }
}

// ---------------- BN2 (finalized inline) + relu + mean pool ----------------
__global__ void k_pool(const float* __restrict__ g2, const float* __restrict__ be2) {
    int b = blockIdx.x >> 5, o = blockIdx.x & 31;
    double n = (double)B_SZ * L2_OUT;
    double md = g_dstats[64 + o] / n;
    double var = g_dstats[96 + o] / n - md * md;
    float rs = (float)rsqrt(var + EPSF);
    float ga = g2[o] * rs;
    float bb = be2[o] - (float)md * ga;
    const float* y = g_y2 + (b * T_CH + o) * L2_OUT;
    float s = 0.f;
    for (int i = threadIdx.x; i < L2_OUT; i += 256) s += fmaxf(y[i] * ga + bb, 0.f);
    __shared__ float sm[256];
    sm[threadIdx.x] = s;
    __syncthreads();
    for (int st = 128; st > 0; st >>= 1) {
        if (threadIdx.x < st) sm[threadIdx.x] += sm[threadIdx.x + st];
        __syncthreads();
    }
    if (threadIdx.x == 0) g_pool[b * T_CH + o] = sm[0] / (float)L2_OUT;
}

// ---------------- FC head ----------------
__global__ void k_fc(const float* __restrict__ fc1_w, const float* __restrict__ fc1_b,
                     const float* __restrict__ fc2_w, const float* __restrict__ fc2_b,
                     float* __restrict__ out) {
    __shared__ float z[B_SZ * H_DIM];
    int t = threadIdx.x;
    for (int i = t; i < B_SZ * H_DIM; i += 256) {
        int b = i >> 6, j = i & 63;
        float acc = fc1_b[j];
#pragma unroll
        for (int c = 0; c < T_CH; c++) acc += g_pool[b * T_CH + c] * fc1_w[c * H_DIM + j];
        z[i] = fmaxf(acc, 0.f);
    }
    __syncthreads();
    for (int i = t; i < B_SZ * NCLS; i += 256) {
        int b = i / NCLS, c = i % NCLS;
        float acc = fc2_b[c];
#pragma unroll
        for (int j = 0; j < H_DIM; j++) acc += z[b * H_DIM + j] * fc2_w[j * NCLS + c];
        out[i] = acc;
    }
}

// ---------------- launcher ----------------
extern "C" void kernel_launch(void* const* d_in, const int* in_sizes, int n_in,
                              void* d_out, int out_size) {
    const float* x      = (const float*)d_in[0];
    const float* ew     = (const float*)d_in[1];
    const float* W1     = (const float*)d_in[2];
    const float* b1     = (const float*)d_in[3];
    const float* W2     = (const float*)d_in[4];
    const float* b2     = (const float*)d_in[5];
    const float* tc1_w  = (const float*)d_in[6];
    const float* tc1_b  = (const float*)d_in[7];
    const float* bn1_g  = (const float*)d_in[8];
    const float* bn1_b  = (const float*)d_in[9];
    const float* tc2_w  = (const float*)d_in[10];
    const float* tc2_b  = (const float*)d_in[11];
    const float* bn2_g  = (const float*)d_in[12];
    const float* bn2_b  = (const float*)d_in[13];
    const float* fc1_w  = (const float*)d_in[14];
    const float* fc1_b  = (const float*)d_in[15];
    const float* fc2_w  = (const float*)d_in[16];
    const float* fc2_b  = (const float*)d_in[17];
    const int*   ei     = (const int*)d_in[18];
    float* out = (float*)d_out;

    // CSR build (shared by both GCN layers)
    k_init<<<N_NODES / 256, 256>>>();
    k_deg_hist<<<N_EDGES / 256, 256>>>(ei, ew);
    k_scan1<<<256, 256>>>();
    k_scan23<<<256, 256>>>();
    k_place<<<N_EDGES / 256, 256>>>(ei, ew);

    // GCN layer 1: aggregate x (22-dim) then transform (+bias+relu)
    k_gather22<<<N_NODES * 32 / 256, 256>>>(x);
    k_gemm1<<<N_NODES / 32, 256>>>(W1, b1);

    // GCN layer 2: transform (fp16 out) then aggregate (+bias+relu)
    k_gemm2<<<N_NODES / 32, 256>>>(W2);
    k_gather64<<<N_NODES * 32 / 256, 256>>>(b2);

    // temporal convs with fused BN stats
    k_conv1<<<dim3((L1_OUT + 63) / 64, B_SZ), 256>>>(tc1_w, tc1_b);
    k_conv2<<<dim3((L2_OUT + 63) / 64, B_SZ), 256>>>(tc2_w, tc2_b, bn1_g, bn1_b);

    // BN2 + relu + pool, FC head
    k_pool<<<B_SZ * T_CH, 256>>>(bn2_g, bn2_b);
    k_fc<<<1, 256>>>(fc1_w, fc1_b, fc2_w, fc2_b, out);
}

// round 5
// speedup vs baseline: 2.6682x; 1.1248x over previous
#include <cuda_runtime.h>
#include <cuda_fp16.h>

// Problem constants (fixed shapes)
#define N_NODES 65536
#define N_EDGES 1048576
#define C_IN    22
#define H_DIM   64
#define B_SZ    16
#define L_SEQ   4096
#define T_CH    32
#define KW      3
#define L1_OUT  4098
#define L2_OUT  4100
#define NCLS    3
#define EPSF    1e-5

#define CNT_SHIFT 42
#define FIX_SCALE 16777216.0f   // 2^24

// ---------------- scratch ----------------
__device__ unsigned long long g_pack[N_NODES]; // count<<42 | fixpoint(deg_extra, 2^24)
__device__ float   g_aggx[N_NODES * C_IN];
__device__ float   g_buf1[N_NODES * H_DIM];
__device__ __half  g_hbuf[N_NODES * H_DIM];
__device__ float   g_dinv[N_NODES];
__device__ int     g_off[N_NODES + 1];
__device__ int     g_cursor[N_NODES];
__device__ int     g_bsum[256];
__device__ int2    g_edge[N_EDGES];
__device__ float   g_y1[B_SZ * T_CH * L1_OUT];
__device__ float   g_y2[B_SZ * T_CH * L2_OUT];
__device__ double  g_dstats[128];
__device__ float   g_pool[B_SZ * T_CH];
__device__ int     g_done;

// ---------------- fused degree+count histogram (one 64-bit RED per edge) ----
__global__ void k_deg_hist(const int* __restrict__ ei, const float* __restrict__ ew) {
    int e = blockIdx.x * blockDim.x + threadIdx.x;
    if (e < N_EDGES) {
        int c = ei[N_EDGES + e];
        unsigned long long fx = (unsigned long long)(ew[e] * FIX_SCALE + 0.5f);
        atomicAdd(&g_pack[c], (1ULL << CNT_SHIFT) | fx);
    }
}

// ---------------- scan phase 1 (+ dinv finalize, + stats/done zero) --------
__global__ void k_scan1() {
    __shared__ int s[256];
    int tid = threadIdx.x;
    int i = blockIdx.x * 256 + tid;
    if (blockIdx.x == 0) {
        if (tid < 128) g_dstats[tid] = 0.0;
        if (tid == 128) g_done = 0;
    }
    unsigned long long pk = g_pack[i];
    int v = (int)(pk >> CNT_SHIFT);
    float deg = 1.0f + (float)(pk & ((1ULL << CNT_SHIFT) - 1)) * (1.0f / FIX_SCALE);
    g_dinv[i] = rsqrtf(deg);
    s[tid] = v;
    __syncthreads();
    for (int st = 1; st < 256; st <<= 1) {
        int a = (tid >= st) ? s[tid - st] : 0;
        __syncthreads();
        s[tid] += a;
        __syncthreads();
    }
    g_off[i] = s[tid] - v;
    if (tid == 255) g_bsum[blockIdx.x] = s[255];
}

// ---------------- scan phases 2+3 merged ----------------
__global__ void k_scan23() {
    __shared__ int s[256];
    int tid = threadIdx.x;
    s[tid] = (tid < (int)blockIdx.x) ? g_bsum[tid] : 0;
    __syncthreads();
    for (int st = 128; st > 0; st >>= 1) {
        if (tid < st) s[tid] += s[tid + st];
        __syncthreads();
    }
    int i = blockIdx.x * 256 + tid;
    int o = g_off[i] + s[0];
    g_off[i] = o;
    g_cursor[i] = o;
    if (i == 0) g_off[N_NODES] = N_EDGES;
}

__global__ void k_place(const int* __restrict__ ei, const float* __restrict__ ew) {
    int e = blockIdx.x * blockDim.x + threadIdx.x;
    if (e >= N_EDGES) return;
    int r = ei[e];
    int c = ei[N_EDGES + e];
    float w = g_dinv[r] * ew[e] * g_dinv[c];
    int pos = atomicAdd(&g_cursor[c], 1);
    g_edge[pos] = make_int2(r, __float_as_int(w));
}

// ---------------- layer-1 aggregation on raw x (22 dims) ----------------
__global__ void k_gather22(const float* __restrict__ x) {
    int warp = (blockIdx.x * blockDim.x + threadIdx.x) >> 5;
    int lane = threadIdx.x & 31;
    if (warp >= N_NODES) return;
    bool act = lane < C_IN;
    int beg = g_off[warp], end = g_off[warp + 1];
    float a = 0.f;
    int e = beg;
    for (; e + 1 < end; e += 2) {
        int2 e0 = g_edge[e];
        int2 e1 = g_edge[e + 1];
        float w0 = __int_as_float(e0.y);
        float w1 = __int_as_float(e1.y);
        if (act) {
            a += w0 * x[(size_t)e0.x * C_IN + lane];
            a += w1 * x[(size_t)e1.x * C_IN + lane];
        }
    }
    if (e < end) {
        int2 e0 = g_edge[e];
        float w0 = __int_as_float(e0.y);
        if (act) a += w0 * x[(size_t)e0.x * C_IN + lane];
    }
    float d = g_dinv[warp];
    d = d * d;
    if (act) {
        a += d * x[(size_t)warp * C_IN + lane];
        g_aggx[(size_t)warp * C_IN + lane] = a;
    }
}

// ---------------- aggx @ W1 + b1, relu -> buf1 (64n/block, 4n x 4f/thread) --
__global__ void k_gemm1(const float* __restrict__ W1, const float* __restrict__ b1) {
    __shared__ float sW[C_IN * H_DIM];
    __shared__ float sx[64 * C_IN];
    int t = threadIdx.x;
    int n0 = blockIdx.x * 64;
    for (int i = t; i < C_IN * H_DIM; i += 256) sW[i] = W1[i];
    for (int i = t; i < 64 * C_IN; i += 256) sx[i] = g_aggx[n0 * C_IN + i];
    __syncthreads();
    int tf = t & 15, tn = t >> 4;
    int f4 = tf * 4;
    float acc[4][4];
    float4 bv = *(const float4*)&b1[f4];
#pragma unroll
    for (int j = 0; j < 4; j++) {
        acc[j][0] = bv.x; acc[j][1] = bv.y; acc[j][2] = bv.z; acc[j][3] = bv.w;
    }
#pragma unroll
    for (int c = 0; c < C_IN; c++) {
        float4 wv = *(const float4*)&sW[c * H_DIM + f4];
#pragma unroll
        for (int j = 0; j < 4; j++) {
            float hv = sx[(tn * 4 + j) * C_IN + c];
            acc[j][0] += hv * wv.x; acc[j][1] += hv * wv.y;
            acc[j][2] += hv * wv.z; acc[j][3] += hv * wv.w;
        }
    }
#pragma unroll
    for (int j = 0; j < 4; j++) {
        int n = n0 + tn * 4 + j;
        float4 o;
        o.x = fmaxf(acc[j][0], 0.f); o.y = fmaxf(acc[j][1], 0.f);
        o.z = fmaxf(acc[j][2], 0.f); o.w = fmaxf(acc[j][3], 0.f);
        *(float4*)&g_buf1[n * H_DIM + f4] = o;
    }
}

// ---------------- buf1 @ W2 -> hbuf fp16 (64n/block, 4n x 4f/thread) --------
__global__ void k_gemm2(const float* __restrict__ W2) {
    __shared__ float sW[H_DIM * H_DIM];
    __shared__ float sh[64 * 65];
    int t = threadIdx.x;
    int n0 = blockIdx.x * 64;
    for (int i = t; i < H_DIM * H_DIM; i += 256) {
        sW[i] = W2[i];
        int n = i >> 6, c = i & 63;
        sh[n * 65 + c] = g_buf1[n0 * 64 + i];
    }
    __syncthreads();
    int tf = t & 15, tn = t >> 4;
    int f4 = tf * 4;
    float acc[4][4] = {};
#pragma unroll 8
    for (int c = 0; c < H_DIM; c++) {
        float4 wv = *(const float4*)&sW[c * H_DIM + f4];
#pragma unroll
        for (int j = 0; j < 4; j++) {
            float hv = sh[(tn * 4 + j) * 65 + c];
            acc[j][0] += hv * wv.x; acc[j][1] += hv * wv.y;
            acc[j][2] += hv * wv.z; acc[j][3] += hv * wv.w;
        }
    }
#pragma unroll
    for (int j = 0; j < 4; j++) {
        int n = n0 + tn * 4 + j;
        __half2* p = (__half2*)&g_hbuf[n * H_DIM + f4];
        p[0] = __floats2half2_rn(acc[j][0], acc[j][1]);
        p[1] = __floats2half2_rn(acc[j][2], acc[j][3]);
    }
}

// ---------------- layer-2 CSR gather (fp16 src) + bias + relu -> buf1 -------
__global__ void k_gather64(const float* __restrict__ bias) {
    int warp = (blockIdx.x * blockDim.x + threadIdx.x) >> 5;
    int lane = threadIdx.x & 31;
    if (warp >= N_NODES) return;
    int beg = g_off[warp], end = g_off[warp + 1];
    const __half2* __restrict__ src = (const __half2*)g_hbuf;
    float ax = 0.f, ay = 0.f;
    int e = beg;
    for (; e + 1 < end; e += 2) {
        int2 e0 = g_edge[e];
        int2 e1 = g_edge[e + 1];
        float2 v0 = __half22float2(src[(size_t)e0.x * 32 + lane]);
        float2 v1 = __half22float2(src[(size_t)e1.x * 32 + lane]);
        float w0 = __int_as_float(e0.y);
        float w1 = __int_as_float(e1.y);
        ax += w0 * v0.x + w1 * v1.x;
        ay += w0 * v0.y + w1 * v1.y;
    }
    if (e < end) {
        int2 e0 = g_edge[e];
        float2 v0 = __half22float2(src[(size_t)e0.x * 32 + lane]);
        float w0 = __int_as_float(e0.y);
        ax += w0 * v0.x;
        ay += w0 * v0.y;
    }
    float d = g_dinv[warp];
    d = d * d;
    float2 s = __half22float2(src[(size_t)warp * 32 + lane]);
    ax += d * s.x + bias[lane * 2];
    ay += d * s.y + bias[lane * 2 + 1];
    ((float2*)g_buf1)[(size_t)warp * 32 + lane] =
        make_float2(fmaxf(ax, 0.f), fmaxf(ay, 0.f));
}

// ---------------- conv1 + fused BN1 stat accumulation ----------------
__global__ void k_conv1(const float* __restrict__ w, const float* __restrict__ bias) {
    __shared__ __align__(8) float sw[H_DIM * KW * 34];
    __shared__ float sx[66 * 64];
    __shared__ float s_sum[T_CH], s_sq[T_CH];
    int b = blockIdx.y;
    int t0 = blockIdx.x * 64;
    int t = threadIdx.x;
    if (t < T_CH) { s_sum[t] = 0.f; s_sq[t] = 0.f; }
    for (int j = t; j < T_CH * H_DIM * KW; j += 256) {
        int o = j / (H_DIM * KW), ik = j % (H_DIM * KW);
        sw[ik * 34 + o] = w[j];
    }
    for (int j = t; j < 66 * 64; j += 256) {
        int row = j >> 6, c = j & 63;
        int l = t0 + row - 2;
        sx[j] = (l >= 0 && l < L_SEQ) ? g_buf1[((b << 12) + l) * 64 + c] : 0.f;
    }
    __syncthreads();
    int to = t & 15, tq = t >> 4;
    int o2 = to * 2;
    float acc0[4], acc1[4];
    float b0 = bias[o2], b1v = bias[o2 + 1];
#pragma unroll
    for (int j = 0; j < 4; j++) { acc0[j] = b0; acc1[j] = b1v; }
#pragma unroll
    for (int i = 0; i < H_DIM; i++) {
        float xr[6];
#pragma unroll
        for (int r = 0; r < 6; r++) xr[r] = sx[(4 * tq + r) * 64 + i];
#pragma unroll
        for (int k = 0; k < KW; k++) {
            float2 wv = *(const float2*)&sw[(i * 3 + k) * 34 + o2];
#pragma unroll
            for (int j = 0; j < 4; j++) {
                acc0[j] += xr[j + k] * wv.x;
                acc1[j] += xr[j + k] * wv.y;
            }
        }
    }
    int tb = t0 + 4 * tq;
    float* p0 = &g_y1[(b * T_CH + o2) * L1_OUT + tb];
    float* p1 = &g_y1[(b * T_CH + o2 + 1) * L1_OUT + tb];
    float s0 = 0.f, q0 = 0.f, s1 = 0.f, q1 = 0.f;
    if (tb + 3 < L1_OUT) {
        ((float2*)p0)[0] = make_float2(acc0[0], acc0[1]);
        ((float2*)p0)[1] = make_float2(acc0[2], acc0[3]);
        ((float2*)p1)[0] = make_float2(acc1[0], acc1[1]);
        ((float2*)p1)[1] = make_float2(acc1[2], acc1[3]);
#pragma unroll
        for (int j = 0; j < 4; j++) {
            s0 += acc0[j]; q0 += acc0[j] * acc0[j];
            s1 += acc1[j]; q1 += acc1[j] * acc1[j];
        }
    } else {
#pragma unroll
        for (int j = 0; j < 4; j++)
            if (tb + j < L1_OUT) {
                p0[j] = acc0[j]; p1[j] = acc1[j];
                s0 += acc0[j]; q0 += acc0[j] * acc0[j];
                s1 += acc1[j]; q1 += acc1[j] * acc1[j];
            }
    }
    atomicAdd(&s_sum[o2], s0);     atomicAdd(&s_sq[o2], q0);
    atomicAdd(&s_sum[o2 + 1], s1); atomicAdd(&s_sq[o2 + 1], q1);
    __syncthreads();
    if (t < T_CH) {
        atomicAdd(&g_dstats[t], (double)s_sum[t]);
        atomicAdd(&g_dstats[32 + t], (double)s_sq[t]);
    }
}

// ---------------- conv2 (BN1 inline) + fused BN2 stats ----------------
__global__ void k_conv2(const float* __restrict__ w, const float* __restrict__ bias,
                        const float* __restrict__ g1, const float* __restrict__ be1) {
    __shared__ __align__(8) float sw[T_CH * KW * 34];
    __shared__ float sx[66 * 33];
    __shared__ float s_ga[T_CH], s_bb[T_CH];
    __shared__ float s_sum[T_CH], s_sq[T_CH];
    int b = blockIdx.y;
    int t0 = blockIdx.x * 64;
    int t = threadIdx.x;
    if (t < T_CH) {
        double n = (double)B_SZ * L1_OUT;
        double m = g_dstats[t] / n;
        double var = g_dstats[32 + t] / n - m * m;
        float rs = (float)rsqrt(var + EPSF);
        float ga = g1[t] * rs;
        s_ga[t] = ga;
        s_bb[t] = be1[t] - (float)m * ga;
        s_sum[t] = 0.f; s_sq[t] = 0.f;
    }
    for (int j = t; j < T_CH * T_CH * KW; j += 256) {
        int o = j / (T_CH * KW), ik = j % (T_CH * KW);
        sw[ik * 34 + o] = w[j];
    }
    __syncthreads();
    for (int j = t; j < 32 * 66; j += 256) {
        int i = j / 66, row = j % 66;
        int l = t0 + row - 2;
        float v = 0.f;
        if (l >= 0 && l < L1_OUT)
            v = fmaxf(g_y1[(b * T_CH + i) * L1_OUT + l] * s_ga[i] + s_bb[i], 0.f);
        sx[row * 33 + i] = v;
    }
    __syncthreads();
    int to = t & 15, tq = t >> 4;
    int o2 = to * 2;
    float acc0[4], acc1[4];
    float b0 = bias[o2], b1v = bias[o2 + 1];
#pragma unroll
    for (int j = 0; j < 4; j++) { acc0[j] = b0; acc1[j] = b1v; }
#pragma unroll
    for (int i = 0; i < T_CH; i++) {
        float xr[6];
#pragma unroll
        for (int r = 0; r < 6; r++) xr[r] = sx[(4 * tq + r) * 33 + i];
#pragma unroll
        for (int k = 0; k < KW; k++) {
            float2 wv = *(const float2*)&sw[(i * 3 + k) * 34 + o2];
#pragma unroll
            for (int j = 0; j < 4; j++) {
                acc0[j] += xr[j + k] * wv.x;
                acc1[j] += xr[j + k] * wv.y;
            }
        }
    }
    int tb = t0 + 4 * tq;
    float* p0 = &g_y2[(b * T_CH + o2) * L2_OUT + tb];
    float* p1 = &g_y2[(b * T_CH + o2 + 1) * L2_OUT + tb];
    float s0 = 0.f, q0 = 0.f, s1 = 0.f, q1 = 0.f;
    if (tb + 3 < L2_OUT) {
        ((float2*)p0)[0] = make_float2(acc0[0], acc0[1]);
        ((float2*)p0)[1] = make_float2(acc0[2], acc0[3]);
        ((float2*)p1)[0] = make_float2(acc1[0], acc1[1]);
        ((float2*)p1)[1] = make_float2(acc1[2], acc1[3]);
#pragma unroll
        for (int j = 0; j < 4; j++) {
            s0 += acc0[j]; q0 += acc0[j] * acc0[j];
            s1 += acc1[j]; q1 += acc1[j] * acc1[j];
        }
    } else {
#pragma unroll
        for (int j = 0; j < 4; j++)
            if (tb + j < L2_OUT) {
                p0[j] = acc0[j]; p1[j] = acc1[j];
                s0 += acc0[j]; q0 += acc0[j] * acc0[j];
                s1 += acc1[j]; q1 += acc1[j] * acc1[j];
            }
    }
    atomicAdd(&s_sum[o2], s0);     atomicAdd(&s_sq[o2], q0);
    atomicAdd(&s_sum[o2 + 1], s1); atomicAdd(&s_sq[o2 + 1], q1);
    __syncthreads();
    if (t < T_CH) {
        atomicAdd(&g_dstats[64 + t], (double)s_sum[t]);
        atomicAdd(&g_dstats[96 + t], (double)s_sq[t]);
    }
}

// ---------------- BN2 + relu + mean pool, last block runs FC head ----------
__global__ void k_pool_fc(const float* __restrict__ g2, const float* __restrict__ be2,
                          const float* __restrict__ fc1_w, const float* __restrict__ fc1_b,
                          const float* __restrict__ fc2_w, const float* __restrict__ fc2_b,
                          float* __restrict__ out) {
    int b = blockIdx.x >> 5, o = blockIdx.x & 31;
    double n = (double)B_SZ * L2_OUT;
    double md = g_dstats[64 + o] / n;
    double var = g_dstats[96 + o] / n - md * md;
    float rs = (float)rsqrt(var + EPSF);
    float ga = g2[o] * rs;
    float bb = be2[o] - (float)md * ga;
    const float* y = g_y2 + (b * T_CH + o) * L2_OUT;
    float s = 0.f;
    for (int i = threadIdx.x; i < L2_OUT; i += 256) s += fmaxf(y[i] * ga + bb, 0.f);
    __shared__ float sm[256];
    sm[threadIdx.x] = s;
    __syncthreads();
    for (int st = 128; st > 0; st >>= 1) {
        if (threadIdx.x < st) sm[threadIdx.x] += sm[threadIdx.x + st];
        __syncthreads();
    }
    __shared__ bool last;
    if (threadIdx.x == 0) {
        g_pool[b * T_CH + o] = sm[0] / (float)L2_OUT;
        __threadfence();
        int d = atomicAdd(&g_done, 1);
        last = (d == B_SZ * T_CH - 1);
    }
    __syncthreads();
    if (!last) return;

    // ---- FC head (one block) ----
    __threadfence();
    __shared__ float z[B_SZ * H_DIM];
    int t = threadIdx.x;
    for (int i = t; i < B_SZ * H_DIM; i += 256) {
        int bb2 = i >> 6, j = i & 63;
        float acc = fc1_b[j];
#pragma unroll
        for (int c = 0; c < T_CH; c++)
            acc += __ldcg(&g_pool[bb2 * T_CH + c]) * fc1_w[c * H_DIM + j];
        z[i] = fmaxf(acc, 0.f);
    }
    __syncthreads();
    for (int i = t; i < B_SZ * NCLS; i += 256) {
        int bb2 = i / NCLS, c = i % NCLS;
        float acc = fc2_b[c];
#pragma unroll
        for (int j = 0; j < H_DIM; j++) acc += z[bb2 * H_DIM + j] * fc2_w[j * NCLS + c];
        out[i] = acc;
    }
}

// ---------------- launcher ----------------
extern "C" void kernel_launch(void* const* d_in, const int* in_sizes, int n_in,
                              void* d_out, int out_size) {
    const float* x      = (const float*)d_in[0];
    const float* ew     = (const float*)d_in[1];
    const float* W1     = (const float*)d_in[2];
    const float* b1     = (const float*)d_in[3];
    const float* W2     = (const float*)d_in[4];
    const float* b2     = (const float*)d_in[5];
    const float* tc1_w  = (const float*)d_in[6];
    const float* tc1_b  = (const float*)d_in[7];
    const float* bn1_g  = (const float*)d_in[8];
    const float* bn1_b  = (const float*)d_in[9];
    const float* tc2_w  = (const float*)d_in[10];
    const float* tc2_b  = (const float*)d_in[11];
    const float* bn2_g  = (const float*)d_in[12];
    const float* bn2_b  = (const float*)d_in[13];
    const float* fc1_w  = (const float*)d_in[14];
    const float* fc1_b  = (const float*)d_in[15];
    const float* fc2_w  = (const float*)d_in[16];
    const float* fc2_b  = (const float*)d_in[17];
    const int*   ei     = (const int*)d_in[18];
    float* out = (float*)d_out;

    // zero packed degree/count histogram (capturable async memset)
    void* pack_ptr = nullptr;
    cudaGetSymbolAddress(&pack_ptr, g_pack);
    cudaMemsetAsync(pack_ptr, 0, N_NODES * sizeof(unsigned long long));

    // CSR build (shared by both GCN layers)
    k_deg_hist<<<N_EDGES / 256, 256>>>(ei, ew);
    k_scan1<<<256, 256>>>();
    k_scan23<<<256, 256>>>();
    k_place<<<N_EDGES / 256, 256>>>(ei, ew);

    // GCN layer 1: aggregate x (22-dim) then transform (+bias+relu)
    k_gather22<<<N_NODES * 32 / 256, 256>>>(x);
    k_gemm1<<<N_NODES / 64, 256>>>(W1, b1);

    // GCN layer 2: transform (fp16 out) then aggregate (+bias+relu)
    k_gemm2<<<N_NODES / 64, 256>>>(W2);
    k_gather64<<<N_NODES * 32 / 256, 256>>>(b2);

    // temporal convs with fused BN stats
    k_conv1<<<dim3((L1_OUT + 63) / 64, B_SZ), 256>>>(tc1_w, tc1_b);
    k_conv2<<<dim3((L2_OUT + 63) / 64, B_SZ), 256>>>(tc2_w, tc2_b, bn1_g, bn1_b);

    // BN2 + relu + pool + FC head (fused)
    k_pool_fc<<<B_SZ * T_CH, 256>>>(bn2_g, bn2_b, fc1_w, fc1_b, fc2_w, fc2_b, out);
}